// round 6
// baseline (speedup 1.0000x reference)
#include <cuda_runtime.h>
#include <cuda_bf16.h>

#define BB   16
#define NN   1024
#define FIN  256
#define FOUT 256
#define NEG_INF_V -1000000000.0f
#define SLOPE_V    0.2f

// Scratch (allocation-free rule: __device__ globals)
__device__ float g_Wh[(size_t)BB * NN * FOUT];   // 64 MB
__device__ float g_f1[(size_t)BB * NN];
__device__ float g_f2[(size_t)BB * NN];
__device__ float g_m [(size_t)BB * NN];          // per-row softmax max

// ---------------------------------------------------------------------------
// Kernel 1: Wh = h @ W.  M = B*N = 16384, K = 256, Nout = 256.
// 128x128 block tile, 16-deep K tiles, 8x8 register microtile per thread.
// ---------------------------------------------------------------------------
__global__ __launch_bounds__(256) void gemm_hW(const float* __restrict__ A,
                                               const float* __restrict__ Bm) {
    __shared__ float As[16][128];   // [k][m]
    __shared__ float Bs[16][128];   // [k][n]
    const int tid = threadIdx.x;
    const int m0 = blockIdx.y * 128;
    const int n0 = blockIdx.x * 128;
    const int tx = tid & 15;
    const int ty = tid >> 4;

    float acc[8][8];
#pragma unroll
    for (int i = 0; i < 8; i++)
#pragma unroll
        for (int j = 0; j < 8; j++) acc[i][j] = 0.f;

    for (int k0 = 0; k0 < FIN; k0 += 16) {
#pragma unroll
        for (int t = tid; t < 512; t += 256) {
            int m  = t >> 2;
            int kq = (t & 3) << 2;
            float4 v = *(const float4*)(A + (size_t)(m0 + m) * FIN + k0 + kq);
            As[kq + 0][m] = v.x;
            As[kq + 1][m] = v.y;
            As[kq + 2][m] = v.z;
            As[kq + 3][m] = v.w;
        }
#pragma unroll
        for (int t = tid; t < 512; t += 256) {
            int k  = t >> 5;
            int n4 = (t & 31) << 2;
            *(float4*)&Bs[k][n4] =
                *(const float4*)(Bm + (size_t)(k0 + k) * FOUT + n0 + n4);
        }
        __syncthreads();

#pragma unroll
        for (int k = 0; k < 16; k++) {
            float af[8], bf[8];
            *(float4*)&af[0] = *(float4*)&As[k][ty * 8];
            *(float4*)&af[4] = *(float4*)&As[k][ty * 8 + 4];
            *(float4*)&bf[0] = *(float4*)&Bs[k][tx * 8];
            *(float4*)&bf[4] = *(float4*)&Bs[k][tx * 8 + 4];
#pragma unroll
            for (int i = 0; i < 8; i++)
#pragma unroll
                for (int j = 0; j < 8; j++) acc[i][j] += af[i] * bf[j];
        }
        __syncthreads();
    }

#pragma unroll
    for (int i = 0; i < 8; i++) {
        float* orow = g_Wh + (size_t)(m0 + ty * 8 + i) * FOUT + n0 + tx * 8;
        *(float4*)orow       = make_float4(acc[i][0], acc[i][1], acc[i][2], acc[i][3]);
        *(float4*)(orow + 4) = make_float4(acc[i][4], acc[i][5], acc[i][6], acc[i][7]);
    }
}

// ---------------------------------------------------------------------------
// Kernel 1b: f1 = Wh @ a1, f2 = Wh @ a2.  One warp per row.
// ---------------------------------------------------------------------------
__global__ __launch_bounds__(256) void f12_kernel(const float* __restrict__ a) {
    const int w    = threadIdx.x >> 5;
    const int lane = threadIdx.x & 31;
    const int row  = blockIdx.x * 8 + w;
    const float* wh = g_Wh + (size_t)row * FOUT;
    float s1 = 0.f, s2 = 0.f;
#pragma unroll
    for (int k = 0; k < 8; k++) {
        int c = lane + 32 * k;
        float v = wh[c];
        s1 += v * a[c];
        s2 += v * a[FOUT + c];
    }
#pragma unroll
    for (int off = 16; off; off >>= 1) {
        s1 += __shfl_xor_sync(0xffffffffu, s1, off);
        s2 += __shfl_xor_sync(0xffffffffu, s2, off);
    }
    if (lane == 0) {
        g_f1[row] = s1;
        g_f2[row] = s2;
    }
}

// ---------------------------------------------------------------------------
// Kernel 1c: per-row softmax max via monotonicity of leaky_relu:
//   m_i = leaky_relu(f1_i + max_{j: adj_ij != 0} f2_j)
// One warp per row; int4-vectorized adj scan (memory bound, ~67 MB total).
// If a row has no neighbors, m_i = NEG_INF (matches reference's uniform
// softmax over all-NEG_INF scores: p = exp(0) = 1 for every j).
// ---------------------------------------------------------------------------
__global__ __launch_bounds__(256) void rowmax_kernel(const int* __restrict__ adj) {
    const int w    = threadIdx.x >> 5;
    const int lane = threadIdx.x & 31;
    const int b    = blockIdx.y;
    const int row  = blockIdx.x * 8 + w;

    const int4*  arow = (const int4*)(adj + ((size_t)b * NN + row) * NN);
    const float* f2b  = g_f2 + (size_t)b * NN;

    float m2 = -3.0e38f;
#pragma unroll
    for (int k = 0; k < 8; k++) {
        const int idx = lane + 32 * k;            // int4 index
        const int4   av = arow[idx];
        const float4 fv = *(const float4*)(f2b + idx * 4);
        if (av.x) m2 = fmaxf(m2, fv.x);
        if (av.y) m2 = fmaxf(m2, fv.y);
        if (av.z) m2 = fmaxf(m2, fv.z);
        if (av.w) m2 = fmaxf(m2, fv.w);
    }
#pragma unroll
    for (int off = 16; off; off >>= 1)
        m2 = fmaxf(m2, __shfl_xor_sync(0xffffffffu, m2, off));

    if (lane == 0) {
        float m;
        if (m2 == -3.0e38f) {
            m = NEG_INF_V;                         // isolated row -> uniform
        } else {
            const float s = g_f1[(size_t)b * NN + row] + m2;
            m = (s >= 0.f) ? s : SLOPE_V * s;      // leaky_relu
        }
        g_m[(size_t)b * NN + row] = m;
    }
}

// ---------------------------------------------------------------------------
// Kernel 2: fused masked-softmax + attn@Wh, SINGLE PASS (row max precomputed).
// Block = 8 warps, each warp owns 4 output rows (32 rows/block).
// j in tiles of 32; Wh tile (32x256 f32 = 32KB) staged in SMEM, shared by all
// warps. Lane l owns output channels [4l,4l+4) and [128+4l, 128+4l+4).
// lsum accumulated per-lane, reduced once at the end — no per-tile shfl trees,
// no accumulator rescaling.
// ---------------------------------------------------------------------------
__global__ __launch_bounds__(256) void attn_kernel(const int* __restrict__ adj,
                                                   float* __restrict__ out) {
    __shared__ __align__(16) float whs[32][256];
    const int tid  = threadIdx.x;
    const int w    = tid >> 5;
    const int lane = tid & 31;
    const int b    = blockIdx.y;
    const int i0   = blockIdx.x * 32 + w * 4;

    const float* Whb  = g_Wh + (size_t)b * NN * FOUT;
    const int*   adjb = adj  + (size_t)b * NN * NN;
    const float* f2b  = g_f2 + (size_t)b * NN;

    float acc[4][8];
#pragma unroll
    for (int r = 0; r < 4; r++)
#pragma unroll
        for (int q = 0; q < 8; q++) acc[r][q] = 0.f;

    float lsum[4], f1r[4], mr[4];
#pragma unroll
    for (int r = 0; r < 4; r++) {
        lsum[r] = 0.f;
        f1r[r]  = g_f1[(size_t)b * NN + i0 + r];
        mr[r]   = g_m [(size_t)b * NN + i0 + r];
    }

    for (int j0 = 0; j0 < NN; j0 += 32) {
        __syncthreads();   // protect whs from previous iteration's readers
#pragma unroll
        for (int t = tid; t < 2048; t += 256) {
            int j  = t >> 6;
            int c4 = (t & 63) << 2;
            *(float4*)&whs[j][c4] =
                *(const float4*)(Whb + (size_t)(j0 + j) * FOUT + c4);
        }
        __syncthreads();

        const float f2v = f2b[j0 + lane];
        float pr[4];
#pragma unroll
        for (int r = 0; r < 4; r++) {
            const int i = i0 + r;
            float s = f1r[r] + f2v;
            float e = (s >= 0.f) ? s : SLOPE_V * s;
            if (adjb[(size_t)i * NN + j0 + lane] == 0) e = NEG_INF_V;
            const float p = __expf(e - mr[r]);     // exact flash exponent
            lsum[r] += p;                          // per-lane partial
            pr[r] = p;
        }

        // acc[r][:] += p_j * Wh[j][:]
#pragma unroll
        for (int jj = 0; jj < 32; jj++) {
            const float4 wlo = *(float4*)&whs[jj][lane << 2];
            const float4 whi = *(float4*)&whs[jj][128 + (lane << 2)];
#pragma unroll
            for (int r = 0; r < 4; r++) {
                const float pj = __shfl_sync(0xffffffffu, pr[r], jj);
                acc[r][0] += pj * wlo.x;
                acc[r][1] += pj * wlo.y;
                acc[r][2] += pj * wlo.z;
                acc[r][3] += pj * wlo.w;
                acc[r][4] += pj * whi.x;
                acc[r][5] += pj * whi.y;
                acc[r][6] += pj * whi.z;
                acc[r][7] += pj * whi.w;
            }
        }
    }

    // one warp-reduce of lsum per row, then scale + write
#pragma unroll
    for (int r = 0; r < 4; r++) {
        float s = lsum[r];
#pragma unroll
        for (int off = 16; off; off >>= 1)
            s += __shfl_xor_sync(0xffffffffu, s, off);
        const float inv = 1.f / s;
        float* orow = out + ((size_t)b * NN + i0 + r) * FOUT;
        float4 lo = make_float4(acc[r][0] * inv, acc[r][1] * inv,
                                acc[r][2] * inv, acc[r][3] * inv);
        float4 hi = make_float4(acc[r][4] * inv, acc[r][5] * inv,
                                acc[r][6] * inv, acc[r][7] * inv);
        *(float4*)(orow + (lane << 2))       = lo;
        *(float4*)(orow + 128 + (lane << 2)) = hi;
    }
}

// ---------------------------------------------------------------------------
extern "C" void kernel_launch(void* const* d_in, const int* in_sizes, int n_in,
                              void* d_out, int out_size) {
    const float* h   = (const float*)d_in[0];   // [16,1024,256] f32
    const int*   adj = (const int*)  d_in[1];   // [16,1024,1024] i32
    const float* W   = (const float*)d_in[2];   // [256,256] f32
    const float* a   = (const float*)d_in[3];   // [512] f32
    float* out = (float*)d_out;                 // [16,1024,256] f32

    dim3 g1(FOUT / 128, (BB * NN) / 128);       // (2, 128)
    gemm_hW<<<g1, 256>>>(h, W);

    f12_kernel<<<(BB * NN) / 8, 256>>>(a);

    dim3 gm(NN / 8, BB);                         // (128, 16)
    rowmax_kernel<<<gm, 256>>>(adj);

    dim3 g2(NN / 32, BB);                        // (32, 16)
    attn_kernel<<<g2, 256>>>(adj, out);
}